// round 8
// baseline (speedup 1.0000x reference)
#include <cuda_runtime.h>
#include <cstdint>
#include <math.h>

// ============================================================================
// libdevice-matching transcendentals
// ============================================================================
#if defined(__USE_FAST_MATH__)
__device__ __forceinline__ float xlogf(float x){ return (float)log((double)x); }
__device__ __forceinline__ float xlog1pf(float x){ return (float)log1p((double)x); }
__device__ __forceinline__ float xexpf(float x){ return (float)exp((double)x); }
#else
__device__ __forceinline__ float xlogf(float x){ return logf(x); }
__device__ __forceinline__ float xlog1pf(float x){ return log1pf(x); }
__device__ __forceinline__ float xexpf(float x){ return expf(x); }
#endif

// ============================================================================
// Threefry-2x32 (exact JAX partitionable replication)
// ============================================================================
#define TF_C 0x1BD11BDAu

struct U2 { uint32_t a, b; };

__device__ __forceinline__ uint32_t rotl32(uint32_t x, int r){
    return __funnelshift_l(x, x, r);
}

__device__ __forceinline__ U2 threefry(uint32_t k0, uint32_t k1, uint32_t x0, uint32_t x1){
    uint32_t k2 = k0 ^ k1 ^ TF_C;
    x0 += k0; x1 += k1;
#define TFR(r) { x0 += x1; x1 = rotl32(x1, (r)); x1 ^= x0; }
    TFR(13) TFR(15) TFR(26) TFR(6)
    x0 += k1; x1 += k2 + 1u;
    TFR(17) TFR(29) TFR(16) TFR(24)
    x0 += k2; x1 += k0 + 2u;
    TFR(13) TFR(15) TFR(26) TFR(6)
    x0 += k0; x1 += k1 + 3u;
    TFR(17) TFR(29) TFR(16) TFR(24)
    x0 += k1; x1 += k2 + 4u;
    TFR(13) TFR(15) TFR(26) TFR(6)
    x0 += k2; x1 += k0 + 5u;
#undef TFR
    U2 r; r.a = x0; r.b = x1; return r;
}

__device__ __forceinline__ uint32_t tf_bits(uint32_t k0, uint32_t k1, uint32_t idx){
    U2 o = threefry(k0, k1, 0u, idx);
    return o.a ^ o.b;
}

__device__ __forceinline__ float u01(uint32_t bits){
    return __uint_as_float((bits >> 9) | 0x3f800000u) - 1.0f;
}

// XLA ErfInv32 (Giles polynomial)
__device__ __forceinline__ float erfinv_xla(float x){
    float w = -xlog1pf(-x * x);
    float p;
    if (w < 5.0f){
        w = w - 2.5f;
        p = 2.81022636e-08f;
        p = fmaf(p, w, 3.43273939e-07f);
        p = fmaf(p, w, -3.5233877e-06f);
        p = fmaf(p, w, -4.39150654e-06f);
        p = fmaf(p, w, 0.00021858087f);
        p = fmaf(p, w, -0.00125372503f);
        p = fmaf(p, w, -0.00417768164f);
        p = fmaf(p, w, 0.246640727f);
        p = fmaf(p, w, 1.50140941f);
    } else {
        w = sqrtf(w) - 3.0f;
        p = -0.000200214257f;
        p = fmaf(p, w, 0.000100950558f);
        p = fmaf(p, w, 0.00134934322f);
        p = fmaf(p, w, -0.00367342844f);
        p = fmaf(p, w, 0.00573950773f);
        p = fmaf(p, w, -0.0076224613f);
        p = fmaf(p, w, 0.00943887047f);
        p = fmaf(p, w, 1.00167406f);
        p = fmaf(p, w, 2.83297682f);
    }
    return p * x;
}

// ============================================================================
// packed f32x2 helpers
// ============================================================================
__device__ __forceinline__ unsigned long long pk2(float x, float y){
    unsigned long long r;
    asm("mov.b64 %0, {%1, %2};" : "=l"(r) : "f"(x), "f"(y));
    return r;
}
__device__ __forceinline__ void fma2(unsigned long long& d, unsigned long long a, unsigned long long b){
    asm("fma.rn.f32x2 %0, %1, %2, %0;" : "+l"(d) : "l"(a), "l"(b));
}
__device__ __forceinline__ void add2(unsigned long long& d, unsigned long long a){
    asm("add.rn.f32x2 %0, %0, %1;" : "+l"(d) : "l"(a));
}
__device__ __forceinline__ float2 upk2(unsigned long long v){
    float2 r;
    asm("mov.b64 {%0, %1}, %2;" : "=f"(r.x), "=f"(r.y) : "l"(v));
    return r;
}

// ============================================================================
// Device scratch + constant weights (W1 = 512x32 f32 = exactly 64 KB)
// ============================================================================
__device__ uint2 g_k1[64];
__device__ uint2 g_k2[64];
__device__ uint2 g_kv;
__device__ float g_z[4194304];         // [B][32] final z vectors
__constant__ ulonglong2 c_W1[4096];    // [512][8] packed f32x2 pairs

// ============================================================================
// Kernel 1: RNG keys (partitionable semantics)
// ============================================================================
__global__ void k_setup(const int* __restrict__ seedp){
    int i = threadIdx.x;
    uint32_t s = (uint32_t)seedp[0];
    if (i < 50){
        U2 fk = threefry(0u, s, 0u, (uint32_t)i);
        U2 kw = threefry(fk.a, fk.b, 0u, 0u);
        U2 kr = threefry(fk.a, fk.b, 0u, 1u);
        g_k1[i] = make_uint2(kw.a, kw.b);
        g_k2[i] = make_uint2(kr.a, kr.b);
    } else if (i == 50){
        U2 kv = threefry(0u, s, 0u, 10000u);
        g_kv = make_uint2(kv.a, kv.b);
    }
}

// ============================================================================
// Kernel 2 (R4 proven): encode GEMM [B,512]x[512,33] -> mu (l2norm) + kappa
// 2 rows/thread, k-chunks of 32. d_out: [out B*7 | mu B*32 | kappa B]
// ============================================================================
__global__ void __launch_bounds__(256, 2) k_gemm1(
    const float* __restrict__ h,
    const float* __restrict__ Wmu, const float* __restrict__ bmu,
    const float* __restrict__ Wk,  const float* __restrict__ bk,
    float* __restrict__ outp, int B)
{
    extern __shared__ float sm[];
    float* hs = sm;                  // 512 x 33
    float* Wt = sm + 512 * 33;       // 32 x 36 (transposed, padded)

    const int tid  = threadIdx.x;
    const int row0 = blockIdx.x * 512;

    for (int idx = tid; idx < 32 * 36; idx += 256) Wt[idx] = 0.0f;

    unsigned long long a0[18], a1[18];
#pragma unroll
    for (int j = 0; j < 18; j++){ a0[j] = 0ull; a1[j] = 0ull; }

    const float4* h4 = (const float4*)h;

    for (int c = 0; c < 16; c++){
        __syncthreads();
        for (int idx = tid; idx < 1056; idx += 256){
            int j  = idx >> 5;
            int kk = idx & 31;
            float v = (j < 32) ? Wmu[j * 512 + c * 32 + kk] : Wk[c * 32 + kk];
            Wt[kk * 36 + j] = v;
        }
#pragma unroll
        for (int it = 0; it < 16; it++){
            int lin = tid + it * 256;
            int r = lin >> 3, q = lin & 7;
            float4 v = h4[(size_t)(row0 + r) * 128 + (size_t)(c * 8 + q)];
            float* dst = &hs[r * 33 + q * 4];
            dst[0] = v.x; dst[1] = v.y; dst[2] = v.z; dst[3] = v.w;
        }
        __syncthreads();

        const int b0 = tid * 33;
        const int b1 = (tid + 256) * 33;
#pragma unroll 2
        for (int kk = 0; kk < 32; kk++){
            float hv0 = hs[b0 + kk];
            float hv1 = hs[b1 + kk];
            unsigned long long h0 = pk2(hv0, hv0);
            unsigned long long h1 = pk2(hv1, hv1);
            const ulonglong2* wr = (const ulonglong2*)&Wt[kk * 36];
#pragma unroll
            for (int j = 0; j < 9; j++){
                ulonglong2 t = wr[j];
                fma2(a0[2 * j],     h0, t.x);
                fma2(a0[2 * j + 1], h0, t.y);
                fma2(a1[2 * j],     h1, t.x);
                fma2(a1[2 * j + 1], h1, t.y);
            }
        }
    }

#pragma unroll
    for (int rsel = 0; rsel < 2; rsel++){
        const int row = row0 + tid + rsel * 256;
        unsigned long long* ap = rsel ? a1 : a0;
        float acc[36];
#pragma unroll
        for (int j = 0; j < 18; j++){
            float2 t = upk2(ap[j]);
            acc[2 * j] = t.x; acc[2 * j + 1] = t.y;
        }
        float ss = 0.0f;
#pragma unroll
        for (int j = 0; j < 32; j++){
            acc[j] += bmu[j];
            ss = fmaf(acc[j], acc[j], ss);
        }
        float den = fmaxf(sqrtf(ss), 1e-12f);
        size_t muoff = (size_t)B * 7 + (size_t)row * 32;
#pragma unroll
        for (int j = 0; j < 32; j++) outp[muoff + j] = acc[j] / den;

        float x = __fadd_rn(acc[32], bk[0]);
        float sp = __fadd_rn(fmaxf(x, 0.0f), xlog1pf(xexpf(-fabsf(x))));
        outp[(size_t)B * 39 + row] = __fadd_rn(sp, 1.0f);
    }
}

// ============================================================================
// Kernel 3: z preparation — Wood's rejection + inline normals + Householder.
// Light context: ~800B smem, high occupancy. One row per thread.
// ============================================================================
__global__ void __launch_bounds__(256) k_zprep(
    float* __restrict__ outp, int B)
{
    __shared__ uint2 sk1[50];
    __shared__ uint2 sk2[50];

    const int tid = threadIdx.x;
    if (tid < 50)       sk1[tid] = g_k1[tid];
    else if (tid < 100) sk2[tid - 50] = g_k2[tid - 50];
    __syncthreads();

    const int row = blockIdx.x * 256 + tid;
    const uint32_t ub = (uint32_t)row;
    const float kappa = outp[(size_t)B * 39 + row];

    // ---- Wood's rejection loop (exact f32 op order) ----
    float w = 0.0f;
    bool done = false;
    for (int i = 0; i < 50; i++){
        if (__all_sync(0xffffffffu, done)) break;
        if (!done){
            uint2 K1 = sk1[i];
            float u1 = u01(tf_bits(K1.x, K1.y, ub));
            float wc = __fsub_rn(__fmul_rn(2.0f, u1), 1.0f);
            float omw = fmaxf(__fsub_rn(1.0f, __fmul_rn(wc, wc)), 1e-38f);
            float logp = __fadd_rn(__fmul_rn(kappa, wc), __fmul_rn(14.5f, xlogf(omw)));
            uint2 K2 = sk2[i];
            float u2 = u01(tf_bits(K2.x, K2.y, ub));
            float logr = xlogf(__fadd_rn(u2, 1e-38f));
            if (__fadd_rn(logr, kappa) <= logp){ w = wc; done = true; }
        }
    }
    w = fminf(fmaxf(w, -1.0f), 1.0f);

    // ---- inline normals (RNG index e = row*31 + c) ----
    const uint2 kv = g_kv;
    float z[32];
#pragma unroll 1
    for (int c = 0; c < 31; c++){
        uint32_t bits = tf_bits(kv.x, kv.y, (uint32_t)(row * 31 + c));
        float f = u01(bits);
        const float lo = -0.99999994f;
        float u = fmaxf(lo, __fadd_rn(__fmul_rn(f, 2.0f), lo));
        z[c] = __fmul_rn(1.41421356f, erfinv_xla(u));
    }

    // ---- z_tilde = [sqrt(1-w^2) * l2norm(v), w] ----
    {
        float ssn = 0.0f;
#pragma unroll
        for (int c = 0; c < 31; c++) ssn = fmaf(z[c], z[c], ssn);
        float den = fmaxf(sqrtf(ssn), 1e-12f);
        float st  = sqrtf(fmaxf(__fsub_rn(1.0f, __fmul_rn(w, w)), 1e-38f));
        float sc  = st / den;
#pragma unroll
        for (int c = 0; c < 31; c++) z[c] *= sc;
        z[31] = w;
    }

    // ---- Householder: u = l2norm(e_d - mu); z -= 2 (z.u) u ----
    {
        const size_t muoff = (size_t)B * 7 + (size_t)row * 32;
        float uh[32];
        float ssu = 0.0f;
        const float4* mu4 = (const float4*)(outp + muoff);
#pragma unroll
        for (int q = 0; q < 8; q++){
            float4 m = mu4[q];
            float t0 = ((q * 4 + 0) == 31 ? 1.0f : 0.0f) - m.x;
            float t1 = ((q * 4 + 1) == 31 ? 1.0f : 0.0f) - m.y;
            float t2 = ((q * 4 + 2) == 31 ? 1.0f : 0.0f) - m.z;
            float t3 = ((q * 4 + 3) == 31 ? 1.0f : 0.0f) - m.w;
            uh[q * 4 + 0] = t0; uh[q * 4 + 1] = t1;
            uh[q * 4 + 2] = t2; uh[q * 4 + 3] = t3;
            ssu = fmaf(t0, t0, ssu); ssu = fmaf(t1, t1, ssu);
            ssu = fmaf(t2, t2, ssu); ssu = fmaf(t3, t3, ssu);
        }
        float inv = 1.0f / fmaxf(sqrtf(ssu), 1e-12f);
        float dot = 0.0f;
#pragma unroll
        for (int j = 0; j < 32; j++){
            uh[j] *= inv;
            dot = fmaf(z[j], uh[j], dot);
        }
        float d2 = 2.0f * dot;
#pragma unroll
        for (int j = 0; j < 32; j++) z[j] = fmaf(-d2, uh[j], z[j]);
    }

    float4* zd = (float4*)&g_z[(size_t)row * 32];
#pragma unroll
    for (int q = 0; q < 8; q++)
        zd[q] = make_float4(z[q * 4 + 0], z[q * 4 + 1], z[q * 4 + 2], z[q * 4 + 3]);
}

// ============================================================================
// Kernel 4: pure MLP  relu(z@W1^T+b1) -> relu(@W2^T+b2) -> @W3^T+b3
// W1 packed in __constant__, W2^T in smem. 592 x 222 rows = 2 clean waves.
// ============================================================================
#define ROWS_PER_CTA 222

__global__ void __launch_bounds__(256, 2) k_mlp(
    const float* __restrict__ W2, const float* __restrict__ b1,
    const float* __restrict__ b2,
    const float* __restrict__ W3, const float* __restrict__ b3,
    float* __restrict__ outp, int B)
{
    extern __shared__ float sm[];
    float* W2t = sm;                 // [512][32] transposed
    float* b1s = W2t + 16384;        // [512]
    float* b2s = b1s + 512;          // [32]
    float* W3s = b2s + 32;           // [7][32]
    float* b3s = W3s + 224;          // [8]

    const int tid = threadIdx.x;
    for (int i = tid; i < 16384; i += 256){
        int m = i >> 9, hh = i & 511;
        W2t[hh * 32 + m] = W2[i];
    }
    for (int i = tid; i < 512; i += 256) b1s[i] = b1[i];
    if (tid < 32)  b2s[tid] = b2[tid];
    if (tid < 224) W3s[tid] = W3[tid];
    if (tid < 8)   b3s[tid] = (tid < 7) ? b3[tid] : 0.0f;
    __syncthreads();

    int braw = blockIdx.x * ROWS_PER_CTA + tid;
    const bool valid = (tid < ROWS_PER_CTA) && (braw < B);
    const int r = valid ? braw : (B - 1);

    unsigned long long zp[16];
    {
        const float4* zv = (const float4*)&g_z[(size_t)r * 32];
#pragma unroll
        for (int q = 0; q < 8; q++){
            float4 v = zv[q];
            zp[2 * q]     = pk2(v.x, v.y);
            zp[2 * q + 1] = pk2(v.z, v.w);
        }
    }

    unsigned long long x2p[16];
#pragma unroll
    for (int m = 0; m < 16; m++) x2p[m] = pk2(b2s[2 * m], b2s[2 * m + 1]);

#pragma unroll 4
    for (int hh = 0; hh < 512; hh++){
        unsigned long long ac0 = 0ull, ac1 = 0ull, ac2 = 0ull, ac3 = 0ull;
#pragma unroll
        for (int j = 0; j < 8; j += 2){
            ulonglong2 ta = c_W1[(hh << 3) + j];
            ulonglong2 tb = c_W1[(hh << 3) + j + 1];
            fma2(ac0, zp[2 * j],     ta.x);
            fma2(ac1, zp[2 * j + 1], ta.y);
            fma2(ac2, zp[2 * j + 2], tb.x);
            fma2(ac3, zp[2 * j + 3], tb.y);
        }
        add2(ac0, ac2);
        add2(ac1, ac3);
        add2(ac0, ac1);
        float2 rr = upk2(ac0);
        float a = fmaxf(b1s[hh] + (rr.x + rr.y), 0.0f);

        unsigned long long aa = pk2(a, a);
        const ulonglong2* w2r = (const ulonglong2*)&W2t[hh * 32];
#pragma unroll
        for (int m4 = 0; m4 < 8; m4++){
            ulonglong2 t = w2r[m4];
            fma2(x2p[2 * m4],     aa, t.x);
            fma2(x2p[2 * m4 + 1], aa, t.y);
        }
    }

    unsigned long long xr[16];
#pragma unroll
    for (int m = 0; m < 16; m++){
        float2 t = upk2(x2p[m]);
        xr[m] = pk2(fmaxf(t.x, 0.0f), fmaxf(t.y, 0.0f));
    }

    float outv[7];
#pragma unroll
    for (int o = 0; o < 7; o++){
        unsigned long long acc = 0ull;
        const ulonglong2* w3r = (const ulonglong2*)&W3s[o * 32];
#pragma unroll
        for (int m4 = 0; m4 < 8; m4++){
            ulonglong2 t = w3r[m4];
            fma2(acc, xr[2 * m4],     t.x);
            fma2(acc, xr[2 * m4 + 1], t.y);
        }
        float2 rr = upk2(acc);
        outv[o] = b3s[o] + (rr.x + rr.y);
    }
    if (valid){
#pragma unroll
        for (int o = 0; o < 7; o++) outp[(size_t)r * 7 + o] = outv[o];
    }
}

// ============================================================================
// launch
// ============================================================================
extern "C" void kernel_launch(void* const* d_in, const int* in_sizes, int n_in,
                              void* d_out, int out_size)
{
    const float* h    = (const float*)d_in[0];
    const float* Wmu  = (const float*)d_in[1];
    const float* bmu  = (const float*)d_in[2];
    const float* Wk   = (const float*)d_in[3];
    const float* bk   = (const float*)d_in[4];
    const float* W1   = (const float*)d_in[5];
    const float* b1   = (const float*)d_in[6];
    const float* W2   = (const float*)d_in[7];
    const float* b2   = (const float*)d_in[8];
    const float* W3   = (const float*)d_in[9];
    const float* b3   = (const float*)d_in[10];
    const int*   seed = (const int*)d_in[11];

    const int F = 512;
    const int B = in_sizes[0] / F;          // 131072
    float* outp = (float*)d_out;

    const int smem2 = (512 * 33 + 32 * 36) * 4;          // 72,192
    const int smem4 = (16384 + 512 + 32 + 224 + 8) * 4;  // 68,640
    cudaFuncSetAttribute(k_gemm1, cudaFuncAttributeMaxDynamicSharedMemorySize, smem2);
    cudaFuncSetAttribute(k_mlp,   cudaFuncAttributeMaxDynamicSharedMemorySize, smem4);

    // W1 -> constant bank pre-packed as f32x2 pairs (raw byte copy)
    cudaMemcpyToSymbolAsync(c_W1, W1, 16384 * sizeof(float), 0,
                            cudaMemcpyDeviceToDevice, 0);

    k_setup<<<1, 64>>>(seed);

    k_gemm1<<<B / 512, 256, smem2>>>(h, Wmu, bmu, Wk, bk, outp, B);

    k_zprep<<<B / 256, 256>>>(outp, B);

    int grid4 = (B + ROWS_PER_CTA - 1) / ROWS_PER_CTA;   // 591 -> pad to 592
    if (grid4 & 1) grid4++;
    k_mlp<<<grid4, 256, smem4>>>(W2, b1, b2, W3, b3, outp, B);
}

// round 9
// speedup vs baseline: 1.1173x; 1.1173x over previous
#include <cuda_runtime.h>
#include <cstdint>
#include <math.h>

// ============================================================================
// libdevice-matching transcendentals
// ============================================================================
#if defined(__USE_FAST_MATH__)
__device__ __forceinline__ float xlogf(float x){ return (float)log((double)x); }
__device__ __forceinline__ float xlog1pf(float x){ return (float)log1p((double)x); }
__device__ __forceinline__ float xexpf(float x){ return (float)exp((double)x); }
#else
__device__ __forceinline__ float xlogf(float x){ return logf(x); }
__device__ __forceinline__ float xlog1pf(float x){ return log1pf(x); }
__device__ __forceinline__ float xexpf(float x){ return expf(x); }
#endif

// ============================================================================
// Threefry-2x32 (exact JAX partitionable replication)
// ============================================================================
#define TF_C 0x1BD11BDAu

struct U2 { uint32_t a, b; };

__device__ __forceinline__ uint32_t rotl32(uint32_t x, int r){
    return __funnelshift_l(x, x, r);
}

__device__ __forceinline__ U2 threefry(uint32_t k0, uint32_t k1, uint32_t x0, uint32_t x1){
    uint32_t k2 = k0 ^ k1 ^ TF_C;
    x0 += k0; x1 += k1;
#define TFR(r) { x0 += x1; x1 = rotl32(x1, (r)); x1 ^= x0; }
    TFR(13) TFR(15) TFR(26) TFR(6)
    x0 += k1; x1 += k2 + 1u;
    TFR(17) TFR(29) TFR(16) TFR(24)
    x0 += k2; x1 += k0 + 2u;
    TFR(13) TFR(15) TFR(26) TFR(6)
    x0 += k0; x1 += k1 + 3u;
    TFR(17) TFR(29) TFR(16) TFR(24)
    x0 += k1; x1 += k2 + 4u;
    TFR(13) TFR(15) TFR(26) TFR(6)
    x0 += k2; x1 += k0 + 5u;
#undef TFR
    U2 r; r.a = x0; r.b = x1; return r;
}

__device__ __forceinline__ uint32_t tf_bits(uint32_t k0, uint32_t k1, uint32_t idx){
    U2 o = threefry(k0, k1, 0u, idx);
    return o.a ^ o.b;
}

__device__ __forceinline__ float u01(uint32_t bits){
    return __uint_as_float((bits >> 9) | 0x3f800000u) - 1.0f;
}

// XLA ErfInv32 (Giles polynomial)
__device__ __forceinline__ float erfinv_xla(float x){
    float w = -xlog1pf(-x * x);
    float p;
    if (w < 5.0f){
        w = w - 2.5f;
        p = 2.81022636e-08f;
        p = fmaf(p, w, 3.43273939e-07f);
        p = fmaf(p, w, -3.5233877e-06f);
        p = fmaf(p, w, -4.39150654e-06f);
        p = fmaf(p, w, 0.00021858087f);
        p = fmaf(p, w, -0.00125372503f);
        p = fmaf(p, w, -0.00417768164f);
        p = fmaf(p, w, 0.246640727f);
        p = fmaf(p, w, 1.50140941f);
    } else {
        w = sqrtf(w) - 3.0f;
        p = -0.000200214257f;
        p = fmaf(p, w, 0.000100950558f);
        p = fmaf(p, w, 0.00134934322f);
        p = fmaf(p, w, -0.00367342844f);
        p = fmaf(p, w, 0.00573950773f);
        p = fmaf(p, w, -0.0076224613f);
        p = fmaf(p, w, 0.00943887047f);
        p = fmaf(p, w, 1.00167406f);
        p = fmaf(p, w, 2.83297682f);
    }
    return p * x;
}

// ============================================================================
// packed f32x2 helpers
// ============================================================================
__device__ __forceinline__ unsigned long long pk2(float x, float y){
    unsigned long long r;
    asm("mov.b64 %0, {%1, %2};" : "=l"(r) : "f"(x), "f"(y));
    return r;
}
__device__ __forceinline__ void fma2(unsigned long long& d, unsigned long long a, unsigned long long b){
    asm("fma.rn.f32x2 %0, %1, %2, %0;" : "+l"(d) : "l"(a), "l"(b));
}
__device__ __forceinline__ void add2(unsigned long long& d, unsigned long long a){
    asm("add.rn.f32x2 %0, %0, %1;" : "+l"(d) : "l"(a));
}
__device__ __forceinline__ float2 upk2(unsigned long long v){
    float2 r;
    asm("mov.b64 {%0, %1}, %2;" : "=f"(r.x), "=f"(r.y) : "l"(v));
    return r;
}

// ============================================================================
// Device scratch + constant weights
// ============================================================================
__device__ uint2 g_k1[64];
__device__ uint2 g_k2[64];
__device__ uint2 g_kv;
__device__ float g_norm[4194304];      // [B][32] raw normals (31 used)
__device__ float g_w1even[8192];       // staging: even W1 rows [256][32]
__constant__ ulonglong2 c_W1e[2048];   // even W1 rows, packed f32x2 [256][8]

// ============================================================================
// Kernel 1: RNG keys (partitionable semantics)
// ============================================================================
__global__ void k_setup(const int* __restrict__ seedp){
    int i = threadIdx.x;
    uint32_t s = (uint32_t)seedp[0];
    if (i < 50){
        U2 fk = threefry(0u, s, 0u, (uint32_t)i);
        U2 kw = threefry(fk.a, fk.b, 0u, 0u);
        U2 kr = threefry(fk.a, fk.b, 0u, 1u);
        g_k1[i] = make_uint2(kw.a, kw.b);
        g_k2[i] = make_uint2(kr.a, kr.b);
    } else if (i == 50){
        U2 kv = threefry(0u, s, 0u, 10000u);
        g_kv = make_uint2(kv.a, kv.b);
    }
}

// pack even W1 rows into staging buffer (then host D2D-copies into c_W1e)
__global__ void k_pack(const float* __restrict__ W1){
    int i = blockIdx.x * 256 + threadIdx.x;
    if (i < 8192) g_w1even[i] = W1[(i >> 5) * 64 + (i & 31)];
}

// ============================================================================
// Kernel 2 (R4 proven): encode GEMM [B,512]x[512,33] -> mu (l2norm) + kappa
// ============================================================================
__global__ void __launch_bounds__(256, 2) k_gemm1(
    const float* __restrict__ h,
    const float* __restrict__ Wmu, const float* __restrict__ bmu,
    const float* __restrict__ Wk,  const float* __restrict__ bk,
    float* __restrict__ outp, int B)
{
    extern __shared__ float sm[];
    float* hs = sm;                  // 512 x 33
    float* Wt = sm + 512 * 33;       // 32 x 36

    const int tid  = threadIdx.x;
    const int row0 = blockIdx.x * 512;

    for (int idx = tid; idx < 32 * 36; idx += 256) Wt[idx] = 0.0f;

    unsigned long long a0[18], a1[18];
#pragma unroll
    for (int j = 0; j < 18; j++){ a0[j] = 0ull; a1[j] = 0ull; }

    const float4* h4 = (const float4*)h;

    for (int c = 0; c < 16; c++){
        __syncthreads();
        for (int idx = tid; idx < 1056; idx += 256){
            int j  = idx >> 5;
            int kk = idx & 31;
            float v = (j < 32) ? Wmu[j * 512 + c * 32 + kk] : Wk[c * 32 + kk];
            Wt[kk * 36 + j] = v;
        }
#pragma unroll
        for (int it = 0; it < 16; it++){
            int lin = tid + it * 256;
            int r = lin >> 3, q = lin & 7;
            float4 v = h4[(size_t)(row0 + r) * 128 + (size_t)(c * 8 + q)];
            float* dst = &hs[r * 33 + q * 4];
            dst[0] = v.x; dst[1] = v.y; dst[2] = v.z; dst[3] = v.w;
        }
        __syncthreads();

        const int b0 = tid * 33;
        const int b1 = (tid + 256) * 33;
#pragma unroll 2
        for (int kk = 0; kk < 32; kk++){
            float hv0 = hs[b0 + kk];
            float hv1 = hs[b1 + kk];
            unsigned long long h0 = pk2(hv0, hv0);
            unsigned long long h1 = pk2(hv1, hv1);
            const ulonglong2* wr = (const ulonglong2*)&Wt[kk * 36];
#pragma unroll
            for (int j = 0; j < 9; j++){
                ulonglong2 t = wr[j];
                fma2(a0[2 * j],     h0, t.x);
                fma2(a0[2 * j + 1], h0, t.y);
                fma2(a1[2 * j],     h1, t.x);
                fma2(a1[2 * j + 1], h1, t.y);
            }
        }
    }

#pragma unroll
    for (int rsel = 0; rsel < 2; rsel++){
        const int row = row0 + tid + rsel * 256;
        unsigned long long* ap = rsel ? a1 : a0;
        float acc[36];
#pragma unroll
        for (int j = 0; j < 18; j++){
            float2 t = upk2(ap[j]);
            acc[2 * j] = t.x; acc[2 * j + 1] = t.y;
        }
        float ss = 0.0f;
#pragma unroll
        for (int j = 0; j < 32; j++){
            acc[j] += bmu[j];
            ss = fmaf(acc[j], acc[j], ss);
        }
        float den = fmaxf(sqrtf(ss), 1e-12f);
        size_t muoff = (size_t)B * 7 + (size_t)row * 32;
#pragma unroll
        for (int j = 0; j < 32; j++) outp[muoff + j] = acc[j] / den;

        float x = __fadd_rn(acc[32], bk[0]);
        float sp = __fadd_rn(fmaxf(x, 0.0f), xlog1pf(xexpf(-fabsf(x))));
        outp[(size_t)B * 39 + row] = __fadd_rn(sp, 1.0f);
    }
}

// ============================================================================
// Kernel 3: normals — RNG index e = b*31+c, stored at stride 32
// ============================================================================
__global__ void __launch_bounds__(256) k_normals(int n){
    int e = blockIdx.x * 256 + threadIdx.x;
    if (e >= n) return;
    uint2 kv = g_kv;
    uint32_t bits = tf_bits(kv.x, kv.y, (uint32_t)e);
    float f = u01(bits);
    const float lo = -0.99999994f;
    float u = fmaxf(lo, __fadd_rn(__fmul_rn(f, 2.0f), lo));
    int b = e / 31, c = e - b * 31;
    g_norm[b * 32 + c] = __fmul_rn(1.41421356f, erfinv_xla(u));
}

// ============================================================================
// Kernel 4: FUSED Wood + Householder + MLP.
// W1 even rows in __constant__, W1 odd rows + W2^T in smem (dual-port weights).
// ============================================================================
#define ROWS_PER_CTA 222

__global__ void __launch_bounds__(256, 2) k_sampler(
    const float* __restrict__ W1, const float* __restrict__ W2,
    const float* __restrict__ b1, const float* __restrict__ b2,
    const float* __restrict__ W3, const float* __restrict__ b3,
    float* __restrict__ outp, int B)
{
    extern __shared__ float sm[];
    float* W1o = sm;                 // [256][32] odd W1 rows
    float* W2t = W1o + 8192;         // [512][32] transposed
    float* b1s = W2t + 16384;        // [512]
    float* b2s = b1s + 512;          // [32]
    float* W3s = b2s + 32;           // [7][32]
    float* b3s = W3s + 224;          // [8]
    uint2* sk1 = (uint2*)(b3s + 8);  // [50]
    uint2* sk2 = sk1 + 50;           // [50]

    const int tid = threadIdx.x;
    for (int i = tid; i < 8192; i += 256)
        W1o[i] = W1[(i >> 5) * 64 + 32 + (i & 31)];     // odd rows
    for (int i = tid; i < 16384; i += 256){
        int m = i >> 9, hh = i & 511;
        W2t[hh * 32 + m] = W2[i];
    }
    for (int i = tid; i < 512; i += 256) b1s[i] = b1[i];
    if (tid < 32)  b2s[tid] = b2[tid];
    if (tid < 224) W3s[tid] = W3[tid];
    if (tid < 8)   b3s[tid] = (tid < 7) ? b3[tid] : 0.0f;
    if (tid < 50)  sk1[tid] = g_k1[tid];
    else if (tid < 100) sk2[tid - 50] = g_k2[tid - 50];
    __syncthreads();

    int braw = blockIdx.x * ROWS_PER_CTA + tid;
    const bool valid = (tid < ROWS_PER_CTA) && (braw < B);
    const int b = valid ? braw : (B - 1);
    const uint32_t ub = (uint32_t)b;

    const float kappa = outp[(size_t)B * 39 + b];

    // ---- Wood's rejection loop (exact f32 op order) ----
    float w = 0.0f;
    bool done = false;
    for (int i = 0; i < 50; i++){
        if (__all_sync(0xffffffffu, done)) break;
        if (!done){
            uint2 K1 = sk1[i];
            float u1 = u01(tf_bits(K1.x, K1.y, ub));
            float wc = __fsub_rn(__fmul_rn(2.0f, u1), 1.0f);
            float omw = fmaxf(__fsub_rn(1.0f, __fmul_rn(wc, wc)), 1e-38f);
            float logp = __fadd_rn(__fmul_rn(kappa, wc), __fmul_rn(14.5f, xlogf(omw)));
            uint2 K2 = sk2[i];
            float u2 = u01(tf_bits(K2.x, K2.y, ub));
            float logr = xlogf(__fadd_rn(u2, 1e-38f));
            if (__fadd_rn(logr, kappa) <= logp){ w = wc; done = true; }
        }
    }
    w = fminf(fmaxf(w, -1.0f), 1.0f);

    // ---- z_tilde = [sqrt(1-w^2) * l2norm(v), w] ----
    float z[32];
    {
        const float4* nv = (const float4*)&g_norm[(size_t)b * 32];
#pragma unroll
        for (int q = 0; q < 8; q++){
            float4 v = nv[q];
            z[q * 4 + 0] = v.x; z[q * 4 + 1] = v.y;
            z[q * 4 + 2] = v.z; z[q * 4 + 3] = v.w;
        }
        z[31] = 0.0f;
        float ssn = 0.0f;
#pragma unroll
        for (int c = 0; c < 31; c++) ssn = fmaf(z[c], z[c], ssn);
        float den = fmaxf(sqrtf(ssn), 1e-12f);
        float st  = sqrtf(fmaxf(__fsub_rn(1.0f, __fmul_rn(w, w)), 1e-38f));
        float sc  = st / den;
#pragma unroll
        for (int c = 0; c < 31; c++) z[c] *= sc;
        z[31] = w;
    }

    // ---- Householder: u = l2norm(e_d - mu); z -= 2 (z.u) u ----
    {
        const size_t muoff = (size_t)B * 7 + (size_t)b * 32;
        float uh[32];
        float ssu = 0.0f;
        const float4* mu4 = (const float4*)(outp + muoff);
#pragma unroll
        for (int q = 0; q < 8; q++){
            float4 m = mu4[q];
            float t0 = ((q * 4 + 0) == 31 ? 1.0f : 0.0f) - m.x;
            float t1 = ((q * 4 + 1) == 31 ? 1.0f : 0.0f) - m.y;
            float t2 = ((q * 4 + 2) == 31 ? 1.0f : 0.0f) - m.z;
            float t3 = ((q * 4 + 3) == 31 ? 1.0f : 0.0f) - m.w;
            uh[q * 4 + 0] = t0; uh[q * 4 + 1] = t1;
            uh[q * 4 + 2] = t2; uh[q * 4 + 3] = t3;
            ssu = fmaf(t0, t0, ssu); ssu = fmaf(t1, t1, ssu);
            ssu = fmaf(t2, t2, ssu); ssu = fmaf(t3, t3, ssu);
        }
        float inv = 1.0f / fmaxf(sqrtf(ssu), 1e-12f);
        float dot = 0.0f;
#pragma unroll
        for (int j = 0; j < 32; j++){
            uh[j] *= inv;
            dot = fmaf(z[j], uh[j], dot);
        }
        float d2 = 2.0f * dot;
#pragma unroll
        for (int j = 0; j < 32; j++) z[j] = fmaf(-d2, uh[j], z[j]);
    }

    // ---- MLP: even hh from const, odd hh from smem (port-interleaved) ----
    unsigned long long zp[16];
#pragma unroll
    for (int l = 0; l < 16; l++) zp[l] = pk2(z[2 * l], z[2 * l + 1]);

    unsigned long long x2p[16];
#pragma unroll
    for (int m = 0; m < 16; m++) x2p[m] = pk2(b2s[2 * m], b2s[2 * m + 1]);

#pragma unroll 2
    for (int hp = 0; hp < 256; hp++){
        // even hidden unit 2*hp — weights from constant port
        {
            const ulonglong2* wa = &c_W1e[hp * 8];
            unsigned long long ac0 = 0ull, ac1 = 0ull, ac2 = 0ull, ac3 = 0ull;
#pragma unroll
            for (int j = 0; j < 4; j++){
                ulonglong2 ta = wa[j];
                ulonglong2 tb = wa[j + 4];
                fma2(ac0, zp[2 * j],     ta.x);
                fma2(ac1, zp[2 * j + 1], ta.y);
                fma2(ac2, zp[2 * j + 8], tb.x);
                fma2(ac3, zp[2 * j + 9], tb.y);
            }
            add2(ac0, ac2);
            add2(ac1, ac3);
            add2(ac0, ac1);
            float2 rr = upk2(ac0);
            float a = fmaxf(b1s[2 * hp] + (rr.x + rr.y), 0.0f);
            unsigned long long aa = pk2(a, a);
            const ulonglong2* w2r = (const ulonglong2*)&W2t[(2 * hp) * 32];
#pragma unroll
            for (int m4 = 0; m4 < 8; m4++){
                ulonglong2 t = w2r[m4];
                fma2(x2p[2 * m4],     aa, t.x);
                fma2(x2p[2 * m4 + 1], aa, t.y);
            }
        }
        // odd hidden unit 2*hp+1 — weights from shared memory
        {
            const ulonglong2* wa = (const ulonglong2*)&W1o[hp * 32];
            unsigned long long ac0 = 0ull, ac1 = 0ull, ac2 = 0ull, ac3 = 0ull;
#pragma unroll
            for (int j = 0; j < 4; j++){
                ulonglong2 ta = wa[j];
                ulonglong2 tb = wa[j + 4];
                fma2(ac0, zp[2 * j],     ta.x);
                fma2(ac1, zp[2 * j + 1], ta.y);
                fma2(ac2, zp[2 * j + 8], tb.x);
                fma2(ac3, zp[2 * j + 9], tb.y);
            }
            add2(ac0, ac2);
            add2(ac1, ac3);
            add2(ac0, ac1);
            float2 rr = upk2(ac0);
            float a = fmaxf(b1s[2 * hp + 1] + (rr.x + rr.y), 0.0f);
            unsigned long long aa = pk2(a, a);
            const ulonglong2* w2r = (const ulonglong2*)&W2t[(2 * hp + 1) * 32];
#pragma unroll
            for (int m4 = 0; m4 < 8; m4++){
                ulonglong2 t = w2r[m4];
                fma2(x2p[2 * m4],     aa, t.x);
                fma2(x2p[2 * m4 + 1], aa, t.y);
            }
        }
    }

    unsigned long long xr[16];
#pragma unroll
    for (int m = 0; m < 16; m++){
        float2 t = upk2(x2p[m]);
        xr[m] = pk2(fmaxf(t.x, 0.0f), fmaxf(t.y, 0.0f));
    }

    float outv[7];
#pragma unroll
    for (int o = 0; o < 7; o++){
        unsigned long long acc = 0ull;
        const ulonglong2* w3r = (const ulonglong2*)&W3s[o * 32];
#pragma unroll
        for (int m4 = 0; m4 < 8; m4++){
            ulonglong2 t = w3r[m4];
            fma2(acc, xr[2 * m4],     t.x);
            fma2(acc, xr[2 * m4 + 1], t.y);
        }
        float2 rr = upk2(acc);
        outv[o] = b3s[o] + (rr.x + rr.y);
    }
    if (valid){
#pragma unroll
        for (int o = 0; o < 7; o++) outp[(size_t)b * 7 + o] = outv[o];
    }
}

// ============================================================================
// launch
// ============================================================================
extern "C" void kernel_launch(void* const* d_in, const int* in_sizes, int n_in,
                              void* d_out, int out_size)
{
    const float* h    = (const float*)d_in[0];
    const float* Wmu  = (const float*)d_in[1];
    const float* bmu  = (const float*)d_in[2];
    const float* Wk   = (const float*)d_in[3];
    const float* bk   = (const float*)d_in[4];
    const float* W1   = (const float*)d_in[5];
    const float* b1   = (const float*)d_in[6];
    const float* W2   = (const float*)d_in[7];
    const float* b2   = (const float*)d_in[8];
    const float* W3   = (const float*)d_in[9];
    const float* b3   = (const float*)d_in[10];
    const int*   seed = (const int*)d_in[11];

    const int F = 512;
    const int B = in_sizes[0] / F;          // 131072
    float* outp = (float*)d_out;

    const int smem2 = (512 * 33 + 32 * 36) * 4;                    // 72,192
    const int smem4 = (8192 + 16384 + 512 + 32 + 224 + 8) * 4 + 100 * 8; // 102,208
    cudaFuncSetAttribute(k_gemm1,   cudaFuncAttributeMaxDynamicSharedMemorySize, smem2);
    cudaFuncSetAttribute(k_sampler, cudaFuncAttributeMaxDynamicSharedMemorySize, smem4);

    k_setup<<<1, 64>>>(seed);

    // pack even W1 rows, then copy into the constant bank (D2D, capture-legal)
    k_pack<<<32, 256>>>(W1);
    void* w1even_addr = nullptr;
    cudaGetSymbolAddress(&w1even_addr, g_w1even);
    cudaMemcpyToSymbolAsync(c_W1e, w1even_addr, 8192 * sizeof(float), 0,
                            cudaMemcpyDeviceToDevice, 0);

    k_gemm1<<<B / 512, 256, smem2>>>(h, Wmu, bmu, Wk, bk, outp, B);

    int n = B * 31;
    k_normals<<<(n + 255) / 256, 256>>>(n);

    int grid4 = (B + ROWS_PER_CTA - 1) / ROWS_PER_CTA;   // 591 -> pad to 592
    if (grid4 & 1) grid4++;
    k_sampler<<<grid4, 256, smem4>>>(W1, W2, b1, b2, W3, b3, outp, B);
}